// round 17
// baseline (speedup 1.0000x reference)
#include <cuda_runtime.h>
#include <cuda_fp16.h>
#include <stdint.h>

#define NCN 100000
#define NRN 100000
#define HD  64
#define EMAX 2000000
#define SCAN_BS 256
#define NSCANB 391   // ceil(100000/256)

// ---------------- scratch (device globals: allocation-free) ----------------
// fp16 message buffers stored as uint4 rows (8 uint4 = 64 halves per row) -> 16B aligned
__device__ uint4  g_t_c4 [(size_t)NCN * HD / 8];   // layer-1 msg c->r
__device__ uint4  g_t_r4 [(size_t)NRN * HD / 8];   // layer-1 msg r->c
__device__ uint4  g_t_c4b[(size_t)NCN * HD / 8];   // layer-2 msg c->r
__device__ uint4  g_t_r4b[(size_t)NRN * HD / 8];   // layer-2 msg r->c
__device__ float  g_s_r[(size_t)NRN * HD];   // self terms (fp32)
__device__ float  g_s_c[(size_t)NCN * HD];
__device__ float  g_h_r[(size_t)NRN * HD];   // layer-1 outputs
__device__ float  g_h_c[(size_t)NCN * HD];
__device__ float  g_u_r[(size_t)NRN * HD];   // decoder inputs (layer-2 outputs)
__device__ float  g_u_c[(size_t)NCN * HD];
__device__ int    g_dg_r[NRN];
__device__ int    g_dg_c[NCN];
__device__ int    g_off_r[NRN];
__device__ int    g_off_c[NCN];
__device__ int    g_cur_r[NRN];
__device__ int    g_cur_c[NCN];
__device__ int    g_csr_cr[EMAX];
__device__ int    g_csr_rc[EMAX];
__device__ int    g_bsum[2 * NSCANB + 2];
// folded decoder weights/biases
__device__ float  g_wc_crl[HD * HD];
__device__ float  g_wc_crr[HD * HD];
__device__ float  g_wc_rcl[HD * HD];
__device__ float  g_wc_rcr[HD * HD];
__device__ float  g_bc_r[HD];
__device__ float  g_bc_c[HD];

// ---- well-defined fp16 bit packing helpers (no punning) ----
__device__ __forceinline__ unsigned pack_h2(float a, float b) {
    unsigned lo = (unsigned)__half_as_ushort(__float2half_rn(a));
    unsigned hi = (unsigned)__half_as_ushort(__float2half_rn(b));
    return lo | (hi << 16);
}
__device__ __forceinline__ float2 unpack_h2(unsigned w) {
    __half2 h = __halves2half2(__ushort_as_half((unsigned short)(w & 0xFFFFu)),
                               __ushort_as_half((unsigned short)(w >> 16)));
    return __half22float2(h);
}

// ---------------- kernels ----------------

__global__ void zero2_k(int4* __restrict__ a, int4* __restrict__ b, int n4) {
    int i = blockIdx.x * blockDim.x + threadIdx.x;
    if (i < n4) a[i] = make_int4(0, 0, 0, 0);
    else if (i < 2 * n4) b[i - n4] = make_int4(0, 0, 0, 0);
}

__global__ void degree2_k(const int* __restrict__ dstA, int* __restrict__ degA,
                          const int* __restrict__ dstB, int* __restrict__ degB, int nE) {
    int i = blockIdx.x * blockDim.x + threadIdx.x;
    if (i < nE) atomicAdd(degA + __ldg(dstA + i), 1);
    else if (i < 2 * nE) atomicAdd(degB + __ldg(dstB + (i - nE)), 1);
}

// --- segmented 3-kernel exclusive scan ---
__global__ void scan_block2_k(const int* __restrict__ inA, int* __restrict__ outA,
                              const int* __restrict__ inB, int* __restrict__ outB,
                              int* __restrict__ bsum, int n) {
    __shared__ int sh[SCAN_BS];
    int b = blockIdx.x;
    const int* in;
    int* out;
    int lb;
    if (b < NSCANB) { in = inA; out = outA; lb = b; }
    else            { in = inB; out = outB; lb = b - NSCANB; }
    int i = lb * SCAN_BS + threadIdx.x;
    int v = (i < n) ? in[i] : 0;
    sh[threadIdx.x] = v;
    __syncthreads();
    for (int off = 1; off < SCAN_BS; off <<= 1) {
        int t = (threadIdx.x >= off) ? sh[threadIdx.x - off] : 0;
        __syncthreads();
        sh[threadIdx.x] += t;
        __syncthreads();
    }
    if (i < n) out[i] = sh[threadIdx.x] - v;
    if (threadIdx.x == SCAN_BS - 1) bsum[b] = sh[threadIdx.x];
}

__global__ void scan_sums2_k(int* __restrict__ bsum) {
    __shared__ int sh[1024];
    int* seg = bsum + blockIdx.x * NSCANB;
    int v = (threadIdx.x < NSCANB) ? seg[threadIdx.x] : 0;
    sh[threadIdx.x] = v;
    __syncthreads();
    for (int off = 1; off < 1024; off <<= 1) {
        int t = (threadIdx.x >= off) ? sh[threadIdx.x - off] : 0;
        __syncthreads();
        sh[threadIdx.x] += t;
        __syncthreads();
    }
    if (threadIdx.x < NSCANB) seg[threadIdx.x] = sh[threadIdx.x] - v;
}

__global__ void scan_add_copy2_k(int* __restrict__ outA, int* __restrict__ curA,
                                 int* __restrict__ outB, int* __restrict__ curB,
                                 const int* __restrict__ bsum, int n) {
    int b = blockIdx.x;
    int* out;
    int* cur;
    int lb;
    if (b < NSCANB) { out = outA; cur = curA; lb = b; }
    else            { out = outB; cur = curB; lb = b - NSCANB; }
    int i = lb * SCAN_BS + threadIdx.x;
    if (i < n) {
        int v = out[i] + bsum[b];
        out[i] = v;
        cur[i] = v;
    }
}

__global__ void csr_fill2_k(const int* __restrict__ srcA, const int* __restrict__ dstA,
                            int* __restrict__ curA, int* __restrict__ csrA,
                            const int* __restrict__ srcB, const int* __restrict__ dstB,
                            int* __restrict__ curB, int* __restrict__ csrB, int nE) {
    int i = blockIdx.x * blockDim.x + threadIdx.x;
    if (i < nE) {
        int d = __ldg(dstA + i);
        int p = atomicAdd(curA + d, 1);
        csrA[p] = __ldg(srcA + i);
    } else if (i < 2 * nE) {
        int j = i - nE;
        int d = __ldg(dstB + j);
        int p = atomicAdd(curB + d, 1);
        csrB[p] = __ldg(srcB + j);
    }
}

// One launch for the whole decoder fold (258 blocks of 64 threads).
__global__ void fold_k(const float* __restrict__ W2crl, const float* __restrict__ W2crr,
                       const float* __restrict__ W2rcl, const float* __restrict__ W2rcr,
                       const float* __restrict__ b2cr,  const float* __restrict__ b2rc,
                       const float* __restrict__ Wd_top, const float* __restrict__ Wd_bot,
                       float* __restrict__ wc_crl, float* __restrict__ wc_crr,
                       float* __restrict__ wc_rcl, float* __restrict__ wc_rcr,
                       float* __restrict__ bc_r, float* __restrict__ bc_c) {
    __shared__ float Ar[HD];
    int b = blockIdx.x, j = threadIdx.x;
    const float *Arow, *B;
    float* Crow;
    if (b < 256) {
        int which = b >> 6, r = b & 63;
        switch (which) {
            case 0: Arow = W2crl + r * HD; B = Wd_bot; Crow = wc_crl + r * HD; break;
            case 1: Arow = W2crr + r * HD; B = Wd_bot; Crow = wc_crr + r * HD; break;
            case 2: Arow = W2rcl + r * HD; B = Wd_top; Crow = wc_rcl + r * HD; break;
            default:Arow = W2rcr + r * HD; B = Wd_top; Crow = wc_rcr + r * HD; break;
        }
    } else if (b == 256) { Arow = b2cr; B = Wd_bot; Crow = bc_r; }
    else                 { Arow = b2rc; B = Wd_top; Crow = bc_c; }
    Ar[j] = Arow[j];
    __syncthreads();
    float s = 0.f;
#pragma unroll 16
    for (int k = 0; k < HD; k++) s += Ar[k] * B[k * HD + j];
    Crow[j] = s;
}

// Y[n,64] = X[n,K] @ W[K,64], fp32 output.
__global__ void gemm_nk(const float* __restrict__ X, const float* __restrict__ W,
                        float* __restrict__ Y, int n, int K) {
    extern __shared__ float Ws[]; // K*64
    for (int i = threadIdx.x; i < K * HD; i += blockDim.x) Ws[i] = W[i];
    __syncthreads();
    int row = blockIdx.x * blockDim.x + threadIdx.x;
    if (row >= n) return;
    float acc[HD];
#pragma unroll
    for (int j = 0; j < HD; j++) acc[j] = 0.f;
    const float* xr = X + (size_t)row * K;
    for (int k = 0; k < K; k += 4) {
        float4 xv = *reinterpret_cast<const float4*>(xr + k);
        float xs[4] = {xv.x, xv.y, xv.z, xv.w};
#pragma unroll
        for (int kk = 0; kk < 4; kk++) {
            const float4* wrow = reinterpret_cast<const float4*>(Ws + (k + kk) * HD);
            float x = xs[kk];
#pragma unroll
            for (int j4 = 0; j4 < HD / 4; j4++) {
                float4 w = wrow[j4];
                acc[j4 * 4 + 0] += x * w.x;
                acc[j4 * 4 + 1] += x * w.y;
                acc[j4 * 4 + 2] += x * w.z;
                acc[j4 * 4 + 3] += x * w.w;
            }
        }
    }
    float4* yr = reinterpret_cast<float4*>(Y + (size_t)row * HD);
#pragma unroll
    for (int j4 = 0; j4 < HD / 4; j4++)
        yr[j4] = make_float4(acc[j4 * 4], acc[j4 * 4 + 1], acc[j4 * 4 + 2], acc[j4 * 4 + 3]);
}

// Same GEMM but fp16-packed output rows (8 uint4 per row).
__global__ void gemm_nk_h(const float* __restrict__ X, const float* __restrict__ W,
                          uint4* __restrict__ Y4, int n, int K) {
    extern __shared__ float Ws[]; // K*64
    for (int i = threadIdx.x; i < K * HD; i += blockDim.x) Ws[i] = W[i];
    __syncthreads();
    int row = blockIdx.x * blockDim.x + threadIdx.x;
    if (row >= n) return;
    float acc[HD];
#pragma unroll
    for (int j = 0; j < HD; j++) acc[j] = 0.f;
    const float* xr = X + (size_t)row * K;
    for (int k = 0; k < K; k += 4) {
        float4 xv = *reinterpret_cast<const float4*>(xr + k);
        float xs[4] = {xv.x, xv.y, xv.z, xv.w};
#pragma unroll
        for (int kk = 0; kk < 4; kk++) {
            const float4* wrow = reinterpret_cast<const float4*>(Ws + (k + kk) * HD);
            float x = xs[kk];
#pragma unroll
            for (int j4 = 0; j4 < HD / 4; j4++) {
                float4 w = wrow[j4];
                acc[j4 * 4 + 0] += x * w.x;
                acc[j4 * 4 + 1] += x * w.y;
                acc[j4 * 4 + 2] += x * w.z;
                acc[j4 * 4 + 3] += x * w.w;
            }
        }
    }
    uint4* yr = Y4 + (size_t)row * 8;
#pragma unroll
    for (int p = 0; p < 8; p++) {
        uint4 v;
        v.x = pack_h2(acc[8 * p + 0], acc[8 * p + 1]);
        v.y = pack_h2(acc[8 * p + 2], acc[8 * p + 3]);
        v.z = pack_h2(acc[8 * p + 4], acc[8 * p + 5]);
        v.w = pack_h2(acc[8 * p + 6], acc[8 * p + 7]);
        yr[p] = v;
    }
}

// Fused gather-aggregate + mean + self + bias (+relu).
// 8 lanes per dst node; each lane loads uint4 (16B = 8 halves) -> one LDG.128
// warp-instruction covers 4 edges (4 x 128B lines). fp32 accumulation, unroll-2.
__global__ void aggregate8_k(const uint4* __restrict__ feat4, const float* __restrict__ self,
                             const float* __restrict__ bias, const int* __restrict__ offs,
                             const int* __restrict__ deg, const int* __restrict__ csr,
                             float* __restrict__ out, int n, int do_relu) {
    int g = (blockIdx.x * blockDim.x + threadIdx.x) >> 3;
    int l = threadIdx.x & 7;
    if (g >= n) return;
    int beg = __ldg(offs + g);
    int dg  = __ldg(deg + g);
    int end = beg + dg;
    float a0[8], a1[8];
#pragma unroll
    for (int j = 0; j < 8; j++) { a0[j] = 0.f; a1[j] = 0.f; }
    int e = beg;
    for (; e + 1 < end; e += 2) {
        int s0 = __ldg(csr + e);
        int s1 = __ldg(csr + e + 1);
        uint4 v0 = __ldg(feat4 + (size_t)s0 * 8 + l);   // 8 uint4 per row
        uint4 v1 = __ldg(feat4 + (size_t)s1 * 8 + l);
        float2 f;
        f = unpack_h2(v0.x); a0[0] += f.x; a0[1] += f.y;
        f = unpack_h2(v0.y); a0[2] += f.x; a0[3] += f.y;
        f = unpack_h2(v0.z); a0[4] += f.x; a0[5] += f.y;
        f = unpack_h2(v0.w); a0[6] += f.x; a0[7] += f.y;
        f = unpack_h2(v1.x); a1[0] += f.x; a1[1] += f.y;
        f = unpack_h2(v1.y); a1[2] += f.x; a1[3] += f.y;
        f = unpack_h2(v1.z); a1[4] += f.x; a1[5] += f.y;
        f = unpack_h2(v1.w); a1[6] += f.x; a1[7] += f.y;
    }
    if (e < end) {
        int s0 = __ldg(csr + e);
        uint4 v0 = __ldg(feat4 + (size_t)s0 * 8 + l);
        float2 f;
        f = unpack_h2(v0.x); a0[0] += f.x; a0[1] += f.y;
        f = unpack_h2(v0.y); a0[2] += f.x; a0[3] += f.y;
        f = unpack_h2(v0.z); a0[4] += f.x; a0[5] += f.y;
        f = unpack_h2(v0.w); a0[6] += f.x; a0[7] += f.y;
    }
    float inv = 1.f / (float)max(dg, 1);
    const float4* self4 = reinterpret_cast<const float4*>(self) + (size_t)g * 16 + l * 2;
    const float4* bias4 = reinterpret_cast<const float4*>(bias) + l * 2;
    float4* out4 = reinterpret_cast<float4*>(out) + (size_t)g * 16 + l * 2;
#pragma unroll
    for (int p = 0; p < 2; p++) {
        float4 sf = self4[p];
        float4 bb = bias4[p];
        float4 o;
        o.x = (a0[p * 4 + 0] + a1[p * 4 + 0]) * inv + sf.x + bb.x;
        o.y = (a0[p * 4 + 1] + a1[p * 4 + 1]) * inv + sf.y + bb.y;
        o.z = (a0[p * 4 + 2] + a1[p * 4 + 2]) * inv + sf.z + bb.z;
        o.w = (a0[p * 4 + 3] + a1[p * 4 + 3]) * inv + sf.w + bb.w;
        if (do_relu) {
            o.x = fmaxf(o.x, 0.f); o.y = fmaxf(o.y, 0.f);
            o.z = fmaxf(o.z, 0.f); o.w = fmaxf(o.w, 0.f);
        }
        out4[p] = o;
    }
}

// 16 lanes per supervision edge
__global__ void decode16_k(const float* __restrict__ u_c, const float* __restrict__ u_r,
                           const int* __restrict__ rows, const int* __restrict__ cols,
                           const float* __restrict__ b1, const float* __restrict__ w2,
                           const float* __restrict__ b2, float* __restrict__ out, int L) {
    int g = (blockIdx.x * blockDim.x + threadIdx.x) >> 4;
    int l = threadIdx.x & 15;
    if (g >= L) return;
    int r = __ldg(rows + g);
    int c = __ldg(cols + g);
    float4 a  = reinterpret_cast<const float4*>(u_c)[(size_t)r * 16 + l];
    float4 b  = reinterpret_cast<const float4*>(u_r)[(size_t)c * 16 + l];
    float4 bb = reinterpret_cast<const float4*>(b1)[l];
    float4 w  = reinterpret_cast<const float4*>(w2)[l];
    float h0 = fmaxf(a.x + b.x + bb.x, 0.f);
    float h1 = fmaxf(a.y + b.y + bb.y, 0.f);
    float h2 = fmaxf(a.z + b.z + bb.z, 0.f);
    float h3 = fmaxf(a.w + b.w + bb.w, 0.f);
    float s = (h0 * w.x + h1 * w.y) + (h2 * w.z + h3 * w.w);
#pragma unroll
    for (int off = 8; off; off >>= 1) s += __shfl_xor_sync(0xffffffffu, s, off);
    if (l == 0) out[g] = s + __ldg(b2);
}

// ---------------- launch ----------------

extern "C" void kernel_launch(void* const* d_in, const int* in_sizes, int n_in,
                              void* d_out, int out_size) {
    const float* x_c   = (const float*)d_in[0];
    const float* x_r   = (const float*)d_in[1];
    const float* W1crl = (const float*)d_in[2];
    const float* W1crr = (const float*)d_in[3];
    const float* b1cr  = (const float*)d_in[4];
    const float* W1rcl = (const float*)d_in[5];
    const float* W1rcr = (const float*)d_in[6];
    const float* b1rc  = (const float*)d_in[7];
    const float* W2crl = (const float*)d_in[8];
    const float* W2crr = (const float*)d_in[9];
    const float* b2cr  = (const float*)d_in[10];
    const float* W2rcl = (const float*)d_in[11];
    const float* W2rcr = (const float*)d_in[12];
    const float* b2rc  = (const float*)d_in[13];
    const float* Wd1   = (const float*)d_in[14];
    const float* bd1   = (const float*)d_in[15];
    const float* Wd2   = (const float*)d_in[16];
    const float* bd2   = (const float*)d_in[17];
    const int*   e_cr  = (const int*)d_in[18];
    const int*   e_rc  = (const int*)d_in[19];
    const int*   e_lab = (const int*)d_in[20];
    const int E_ = in_sizes[18] / 2;
    const int L_ = in_sizes[20] / 2;

    uint4 *t_c4, *t_r4, *t_c4b, *t_r4b;
    float *s_r, *s_c, *h_r, *h_c, *u_r, *u_c;
    float *wc_crl, *wc_crr, *wc_rcl, *wc_rcr, *bc_r, *bc_c;
    int *dg_r, *dg_c, *off_r, *off_c, *cur_r, *cur_c, *csr_cr, *csr_rc, *bsum;
    cudaGetSymbolAddress((void**)&t_c4, g_t_c4);
    cudaGetSymbolAddress((void**)&t_r4, g_t_r4);
    cudaGetSymbolAddress((void**)&t_c4b, g_t_c4b);
    cudaGetSymbolAddress((void**)&t_r4b, g_t_r4b);
    cudaGetSymbolAddress((void**)&s_r, g_s_r);
    cudaGetSymbolAddress((void**)&s_c, g_s_c);
    cudaGetSymbolAddress((void**)&h_r, g_h_r);
    cudaGetSymbolAddress((void**)&h_c, g_h_c);
    cudaGetSymbolAddress((void**)&u_r, g_u_r);
    cudaGetSymbolAddress((void**)&u_c, g_u_c);
    cudaGetSymbolAddress((void**)&dg_r, g_dg_r);
    cudaGetSymbolAddress((void**)&dg_c, g_dg_c);
    cudaGetSymbolAddress((void**)&off_r, g_off_r);
    cudaGetSymbolAddress((void**)&off_c, g_off_c);
    cudaGetSymbolAddress((void**)&cur_r, g_cur_r);
    cudaGetSymbolAddress((void**)&cur_c, g_cur_c);
    cudaGetSymbolAddress((void**)&csr_cr, g_csr_cr);
    cudaGetSymbolAddress((void**)&csr_rc, g_csr_rc);
    cudaGetSymbolAddress((void**)&bsum, g_bsum);
    cudaGetSymbolAddress((void**)&wc_crl, g_wc_crl);
    cudaGetSymbolAddress((void**)&wc_crr, g_wc_crr);
    cudaGetSymbolAddress((void**)&wc_rcl, g_wc_rcl);
    cudaGetSymbolAddress((void**)&wc_rcr, g_wc_rcr);
    cudaGetSymbolAddress((void**)&bc_r, g_bc_r);
    cudaGetSymbolAddress((void**)&bc_c, g_bc_c);

    // streams + events (created once, on the uncaptured correctness call)
    static cudaStream_t s2 = nullptr, s3 = nullptr;
    static cudaEvent_t evFork = nullptr, evCSR = nullptr, evA2 = nullptr,
                       evG7 = nullptr, evA4 = nullptr;
    if (s2 == nullptr) {
        cudaStreamCreateWithFlags(&s2, cudaStreamNonBlocking);
        cudaStreamCreateWithFlags(&s3, cudaStreamNonBlocking);
        cudaEventCreateWithFlags(&evFork, cudaEventDisableTiming);
        cudaEventCreateWithFlags(&evCSR, cudaEventDisableTiming);
        cudaEventCreateWithFlags(&evA2, cudaEventDisableTiming);
        cudaEventCreateWithFlags(&evG7, cudaEventDisableTiming);
        cudaEventCreateWithFlags(&evA4, cudaEventDisableTiming);
    }

    const int NT = 256;
    const int gRow  = (NCN + NT - 1) / NT;
    const int gE2   = (2 * E_ + NT - 1) / NT;
    const int gZ2   = (2 * (NCN / 4) + NT - 1) / NT;
    const int gN8   = (NCN * 8 + NT - 1) / NT;
    const int gL16  = (L_ * 16 + NT - 1) / NT;

    const int* cr_s = e_cr;   const int* cr_d = e_cr + E_;
    const int* rc_s = e_rc;   const int* rc_d = e_rc + E_;
    const int* lb_r = e_lab;  const int* lb_c = e_lab + L_;

    const float* Wd_top = Wd1;
    const float* Wd_bot = Wd1 + HD * HD;

    // ======== FORK (main -> s2, s3) ========
    cudaEventRecord(evFork, 0);
    cudaStreamWaitEvent(s2, evFork, 0);
    cudaStreamWaitEvent(s3, evFork, 0);

    // ---- [1] s3: CSR chain -> evCSR ----
    zero2_k<<<gZ2, NT, 0, s3>>>((int4*)dg_r, (int4*)dg_c, NRN / 4);
    degree2_k<<<gE2, NT, 0, s3>>>(cr_d, dg_r, rc_d, dg_c, E_);
    scan_block2_k<<<2 * NSCANB, SCAN_BS, 0, s3>>>(dg_r, off_r, dg_c, off_c, bsum, NCN);
    scan_sums2_k<<<2, 1024, 0, s3>>>(bsum);
    scan_add_copy2_k<<<2 * NSCANB, SCAN_BS, 0, s3>>>(off_r, cur_r, off_c, cur_c, bsum, NCN);
    csr_fill2_k<<<gE2, NT, 0, s3>>>(cr_s, cr_d, cur_r, csr_cr, rc_s, rc_d, cur_c, csr_rc, E_);
    cudaEventRecord(evCSR, s3);

    // ---- [2] s2: G3, G4; wait evCSR; A2 -> evA2 ----
    gemm_nk_h<<<gRow, NT, 64 * HD * sizeof(float), s2>>>(x_r, W1rcl, t_r4, NRN, 64);
    gemm_nk  <<<gRow, NT, 128 * HD * sizeof(float), s2>>>(x_c, W1rcr, s_c, NCN, 128);
    cudaStreamWaitEvent(s2, evCSR, 0);
    aggregate8_k<<<gN8, NT, 0, s2>>>(t_r4, s_c, b1rc, off_c, dg_c, csr_rc, h_c, NCN, 1);
    cudaEventRecord(evA2, s2);

    // ---- [3] main: fold, G1, G2; wait evCSR; A1; G6, G7 -> evG7 ----
    fold_k<<<258, HD>>>(W2crl, W2crr, W2rcl, W2rcr, b2cr, b2rc, Wd_top, Wd_bot,
                        wc_crl, wc_crr, wc_rcl, wc_rcr, bc_r, bc_c);
    gemm_nk_h<<<gRow, NT, 128 * HD * sizeof(float)>>>(x_c, W1crl, t_c4, NCN, 128);
    gemm_nk  <<<gRow, NT,  64 * HD * sizeof(float)>>>(x_r, W1crr, s_r, NRN, 64);
    cudaStreamWaitEvent(0, evCSR, 0);
    aggregate8_k<<<gN8, NT>>>(t_c4, s_r, b1cr, off_r, dg_r, csr_cr, h_r, NRN, 1);
    gemm_nk  <<<gRow, NT, 64 * HD * sizeof(float)>>>(h_r, wc_crr, s_r, NRN, 64);
    gemm_nk_h<<<gRow, NT, 64 * HD * sizeof(float)>>>(h_r, wc_rcl, t_r4b, NRN, 64);
    cudaEventRecord(evG7, 0);

    // ---- [4] s2: G8; wait evG7; A4 -> evA4 ----
    gemm_nk<<<gRow, NT, 64 * HD * sizeof(float), s2>>>(h_c, wc_rcr, s_c, NCN, 64);
    cudaStreamWaitEvent(s2, evG7, 0);
    aggregate8_k<<<gN8, NT, 0, s2>>>(t_r4b, s_c, bc_c, off_c, dg_c, csr_rc, u_c, NCN, 0);
    cudaEventRecord(evA4, s2);

    // ---- [5] main: wait evA2; G5; A3; wait evA4; decode ----
    cudaStreamWaitEvent(0, evA2, 0);
    gemm_nk_h<<<gRow, NT, 64 * HD * sizeof(float)>>>(h_c, wc_crl, t_c4b, NCN, 64);
    aggregate8_k<<<gN8, NT>>>(t_c4b, s_r, bc_r, off_r, dg_r, csr_cr, u_r, NRN, 0);
    cudaStreamWaitEvent(0, evA4, 0);
    decode16_k<<<gL16, NT>>>(u_c, u_r, lb_r, lb_c, bd1, Wd2, bd2, (float*)d_out, L_);
}